// round 16
// baseline (speedup 1.0000x reference)
#include <cuda_runtime.h>
#include <cuda_fp16.h>
#include <math.h>
#include <stdint.h>

// ---------------- problem constants ----------------
#define BATCH 4096
#define NF    39
#define NE    16
#define NPAIR 741
#define K1    (2 * NPAIR * NE)    // 23712
#define NKT0  741                 // K1/32 k-tiles
#define HID   400
#define K2P   416                 // HID padded for small layers
#define NKT2  13                  // K2P/32
#define EPS   1e-5f

// quantization scales
#define SA0   8192.0f
#define SB0   4096.0f
#define INVS0 (1.0f / (SA0 * SB0))
#define SB2   4096.0f
#define INVS2 (1.0f / SB2)

// ---------------- fp16 2-product GEMM tiling (4-stage, 2 CTAs/SM) ----------------
#define BM 128
#define BN 80
#define A_ROWB 80                 // smem row stride bytes (32 halves + 8 pad halves)
#define OFF_BH  10240             // A: 128*80
#define OFF_BL  16640             // +80*80
#define STAGE   23040
#define NSTAGE  4
#define SMEM_G  (STAGE * NSTAGE + 128)  // + full/empty mbarriers
#define KSPLIT0 9
#define NB      512
#define SQOFF   (HID * NB)

// packed tile sizes (halves)
#define A_TILE_H 5120             // 128 rows * 40 halves
#define B_TILE_H 3200             // 80 rows * 40 halves

// ---------------- scratch (packed tile-major layouts) ----------------
__device__ __half d_a[(size_t)32 * NKT0 * A_TILE_H];      // [mtile][kt][128][40]
__device__ __half d_bh[(size_t)5 * NKT0 * B_TILE_H];      // [ntile][kt][80][40]
__device__ __half d_bl[(size_t)5 * NKT0 * B_TILE_H];
__device__ float d_part[(size_t)KSPLIT0 * BATCH * HID];
__device__ __half d_a2[(size_t)32 * NKT2 * A_TILE_H];
__device__ __half d_w2h[2][(size_t)5 * NKT2 * B_TILE_H];
__device__ __half d_w2l[2][(size_t)5 * NKT2 * B_TILE_H];
__device__ float d_h0[BATCH * HID];
__device__ float d_h1[BATCH * HID];
__device__ float d_h2[BATCH * HID];
__device__ float d_pstat[2 * NB * HID];
__device__ float d_scale[3][HID];
__device__ float d_shift[3][HID];

// ---------------- helpers ----------------
__device__ __forceinline__ uint32_t smem_u32(const void* p) {
    uint32_t a;
    asm("{ .reg .u64 t; cvta.to.shared.u64 t, %1; cvt.u32.u64 %0, t; }" : "=r"(a) : "l"(p));
    return a;
}

#define CP_BULK(dst, src, bytes, mbar) \
    asm volatile("cp.async.bulk.shared::cta.global.mbarrier::complete_tx::bytes [%0], [%1], %2, [%3];" \
        :: "r"(dst), "l"(src), "r"(bytes), "r"(mbar) : "memory")
#define MBAR_INIT(a, c)   asm volatile("mbarrier.init.shared.b64 [%0], %1;" :: "r"(a), "r"(c) : "memory")
#define MBAR_EXPECT(a, b) asm volatile("mbarrier.arrive.expect_tx.shared.b64 _, [%0], %1;" :: "r"(a), "r"(b) : "memory")
#define MBAR_ARRIVE(a)    asm volatile("mbarrier.arrive.shared.b64 _, [%0];" :: "r"(a) : "memory")
#define FENCE_ASYNC()     asm volatile("fence.proxy.async.shared::cta;" ::: "memory")

__device__ __forceinline__ void mbar_wait(uint32_t mbar, uint32_t parity) {
    asm volatile(
        "{\n\t.reg .pred P1;\n\t"
        "WAIT_LOOP_%=:\n\t"
        "mbarrier.try_wait.parity.acquire.cta.shared::cta.b64 P1, [%0], %1, 0x989680;\n\t"
        "@P1 bra.uni WAIT_DONE_%=;\n\t"
        "bra.uni WAIT_LOOP_%=;\n\t"
        "WAIT_DONE_%=:\n\t}"
        :: "r"(mbar), "r"(parity) : "memory");
}

#define LDSM4(r0, r1, r2, r3, a) \
    asm volatile("ldmatrix.sync.aligned.m8n8.x4.shared.b16 {%0,%1,%2,%3}, [%4];" \
        : "=r"(r0), "=r"(r1), "=r"(r2), "=r"(r3) : "r"(a))

__device__ __forceinline__ void mma_f16(float* c, const uint32_t* a, const uint32_t* b) {
    asm volatile(
        "mma.sync.aligned.m16n8k16.row.col.f32.f16.f16.f32 "
        "{%0,%1,%2,%3}, {%4,%5,%6,%7}, {%8,%9}, {%0,%1,%2,%3};"
        : "+f"(c[0]), "+f"(c[1]), "+f"(c[2]), "+f"(c[3])
        : "r"(a[0]), "r"(a[1]), "r"(a[2]), "r"(a[3]), "r"(b[0]), "r"(b[1]));
}

// =====================================================================
// Kernel 1: gather + SENET + bilinear -> packed A tiles (scaled fp16)
// =====================================================================
__global__ __launch_bounds__(256) void fuse_front(
    const int* __restrict__ x,
    const float* __restrict__ emb,
    const float* __restrict__ w1, const float* __restrict__ b1,
    const float* __restrict__ w2, const float* __restrict__ b2,
    const float* __restrict__ Wb1, const float* __restrict__ Wb2,
    __half* __restrict__ a_out)
{
    __shared__ float xe[NF][NE];
    __shared__ float xs[NF][NE];
    __shared__ float p1[NF][NE];
    __shared__ float p2[NF][NE];
    __shared__ float zf[NF], av[NF], af[NF];
    __shared__ unsigned char ii[NPAIR], jj[NPAIR];
    __shared__ int is64;

    const int b = blockIdx.x;
    const int tid = threadIdx.x;

    if (tid == 0) {
        int f64 = 1;
        for (int w = 1; w < 2 * NF; w += 2)
            if (x[w] != 0) { f64 = 0; break; }
        is64 = f64;
    }
    for (int k = tid; k < NPAIR; k += 256) {
        int i = 0, rem = k;
        while (rem >= NF - 1 - i) { rem -= NF - 1 - i; i++; }
        ii[k] = (unsigned char)i;
        jj[k] = (unsigned char)(i + 1 + rem);
    }
    __syncthreads();

    for (int idx = tid; idx < NF * NE; idx += 256) {
        int f = idx >> 4, e = idx & 15;
        int xv = is64 ? x[2 * (b * NF + f)] : x[b * NF + f];
        xe[f][e] = emb[(xv + 1000 * f) * NE + e];
    }
    __syncthreads();

    if (tid < NF) {
        float m = xe[tid][0];
        #pragma unroll
        for (int e = 1; e < NE; e++) m = fmaxf(m, xe[tid][e]);
        zf[tid] = m;
    }
    __syncthreads();
    if (tid < NF) {
        float s = b1[tid];
        for (int j = 0; j < NF; j++) s += zf[j] * w1[tid * NF + j];
        av[tid] = fmaxf(s, 0.0f);
    }
    __syncthreads();
    if (tid < NF) {
        float s = b2[tid];
        for (int j = 0; j < NF; j++) s += av[j] * w2[tid * NF + j];
        af[tid] = fmaxf(s, 0.0f);
    }
    __syncthreads();

    for (int idx = tid; idx < NF * NE; idx += 256) {
        int f = idx >> 4, d = idx & 15;
        float s1 = 0.0f, s2 = 0.0f;
        #pragma unroll
        for (int e = 0; e < NE; e++) {
            float v = xe[f][e];
            s1 += v * Wb1[d * NE + e];
            s2 += v * Wb2[d * NE + e];
        }
        p1[f][d] = s1;
        p2[f][d] = af[f] * s2;
        xs[f][d] = af[f] * xe[f][d];
    }
    __syncthreads();

    // packed half2 stores: dest = [b>>7][kt][b&127][pos]
    const size_t mtb = (size_t)(b >> 7) * NKT0;
    const int mrow = b & 127;
    const int HALF_N = NPAIR * NE / 2;   // 5928
    for (int idx2 = tid; idx2 < HALF_N; idx2 += 256) {
        int k = idx2 >> 3;
        int e = (idx2 & 7) * 2;
        int i = ii[k], j = jj[k];
        float v1a = p1[i][e]     * xe[j][e];
        float v1b = p1[i][e + 1] * xe[j][e + 1];
        float v2a = p2[i][e]     * xs[j][e];
        float v2b = p2[i][e + 1] * xs[j][e + 1];
        int gk0 = idx2 * 2;
        int gk1 = gk0 + NPAIR * NE;
        size_t o0 = (mtb + (gk0 >> 5)) * A_TILE_H + mrow * 40 + (gk0 & 31);
        size_t o1 = (mtb + (gk1 >> 5)) * A_TILE_H + mrow * 40 + (gk1 & 31);
        *(__half2*)(a_out + o0) = __halves2half2(__float2half(v1a * SA0), __float2half(v1b * SA0));
        *(__half2*)(a_out + o1) = __halves2half2(__float2half(v2a * SA0), __float2half(v2b * SA0));
    }
}

// =====================================================================
// Kernel 1b: split mw0 rows into scaled fp16 hi/lo (packed B tiles)
// =====================================================================
__global__ __launch_bounds__(256) void split_b(
    const float* __restrict__ w, __half* __restrict__ bh,
    __half* __restrict__ bl)
{
    size_t i = (size_t)blockIdx.x * 256 + threadIdx.x;
    size_t n = (size_t)HID * K1;
    if (i < n) {
        int row = (int)(i / K1);
        int k   = (int)(i - (size_t)row * K1);
        float t = w[i] * SB0;
        __half h = __float2half(t);
        size_t o = (((size_t)(row / 80) * NKT0 + (k >> 5)) * 80 + (row % 80)) * 40 + (k & 31);
        bh[o] = h;
        bl[o] = __float2half(t - __half2float(h));
    }
}

// =====================================================================
// Kernel 1c: split BOTH small-layer weights -> packed fp16 hi/lo tiles
// =====================================================================
__global__ __launch_bounds__(256) void wsplit2(
    const float* __restrict__ wA, const float* __restrict__ wB,
    __half* __restrict__ hA, __half* __restrict__ lA,
    __half* __restrict__ hB, __half* __restrict__ lB)
{
    int idx = blockIdx.x * 256 + threadIdx.x;    // < HID*K2P
    int row = idx / K2P, col = idx - row * K2P;
    float vA = (col < HID) ? wA[row * HID + col] * SB2 : 0.0f;
    float vB = (col < HID) ? wB[row * HID + col] * SB2 : 0.0f;
    __half a = __float2half(vA);
    __half b = __float2half(vB);
    size_t o = (((size_t)(row / 80) * NKT2 + (col >> 5)) * 80 + (row % 80)) * 40 + (col & 31);
    hA[o] = a; lA[o] = __float2half(vA - __half2float(a));
    hB[o] = b; lB[o] = __float2half(vB - __half2float(b));
}

// =====================================================================
// gemm_f16: 2-product fp16 GEMM, bulk-copy + producer/consumer mbarriers
//   CTA 128x80, BK=32, 4-stage, 2 CTAs/SM; packed tile-major operands
// =====================================================================
__global__ __launch_bounds__(256, 2) void gemm_f16(
    const __half* __restrict__ A,
    const __half* __restrict__ Bh, const __half* __restrict__ Bl,
    float* __restrict__ out, const float* __restrict__ bias,
    float invs, int nkt, int ksplit)
{
    extern __shared__ char smem[];
    const uint32_t sb = smem_u32(smem);
    const uint32_t mbF = sb + STAGE * NSTAGE;        // full[4]
    const uint32_t mbE = mbF + 32;                   // empty[4]
    const int tid  = threadIdx.x;
    const int wid  = tid >> 5;
    const int lane = tid & 31;

    const int nbase = blockIdx.x * BN;
    const int mbase = blockIdx.y * BM;
    const int z     = blockIdx.z;

    const int qt = nkt / ksplit, rt = nkt % ksplit;
    const int t0 = z * qt + (z < rt ? z : rt);
    const int T  = qt + (z < rt ? 1 : 0);

    const size_t aTB = (size_t)blockIdx.y * nkt;
    const size_t bTB = (size_t)blockIdx.x * nkt;

    const int wm = (wid & 3) * 32;
    const int wn = (wid >> 2) * 40;
    const int grp = lane >> 2;
    const int qd  = lane & 3;

    const uint32_t aoff = (uint32_t)((wm + (lane & 15)) * A_ROWB + ((lane >> 4) * 16));
    const int rowB = (lane & 7) + ((lane >> 4) << 3);
    const int kB   = ((lane >> 3) & 1) * 16;
    const uint32_t boff  = (uint32_t)(OFF_BH + (wn + rowB) * A_ROWB + kB);
    // merged bh[4]/bl[4] LDSM4: lanes 0-15 -> Bh region, lanes 16-31 -> Bl region
    const uint32_t boff2m = (uint32_t)(OFF_BH + ((lane < 16) ? 0 : (OFF_BL - OFF_BH))
                                       + (wn + 32 + (lane & 7)) * A_ROWB + kB);

    float acc[2][5][4];
    #pragma unroll
    for (int im = 0; im < 2; im++)
        #pragma unroll
        for (int in = 0; in < 5; in++)
            #pragma unroll
            for (int r = 0; r < 4; r++) acc[im][in][r] = 0.0f;

    auto load_tile = [&](int s, int t) {
        const uint32_t st = sb + s * STAGE;
        const uint32_t mbar = mbF + s * 8;
        MBAR_EXPECT(mbar, (uint32_t)STAGE);
        CP_BULK(st,          A  + (aTB + t) * A_TILE_H, (uint32_t)(A_TILE_H * 2), mbar);
        CP_BULK(st + OFF_BH, Bh + (bTB + t) * B_TILE_H, (uint32_t)(B_TILE_H * 2), mbar);
        CP_BULK(st + OFF_BL, Bl + (bTB + t) * B_TILE_H, (uint32_t)(B_TILE_H * 2), mbar);
    };

    if (tid == 0) {
        #pragma unroll
        for (int s = 0; s < NSTAGE; s++) { MBAR_INIT(mbF + s * 8, 1); MBAR_INIT(mbE + s * 8, 8); }
        FENCE_ASYNC();
        load_tile(0, t0);
        load_tile(1, t0 + 1);
        load_tile(2, t0 + 2);
    }
    __syncthreads();

    for (int u = 0; u < T; ++u) {
        const int s = u & 3;

        // producer: wait stage empty (all 8 warps done with its previous lap), refill
        if (tid == 0 && u + 3 < T) {
            const int f = u + 3;
            mbar_wait(mbE + (f & 3) * 8, 1u ^ ((uint32_t)(f >> 2) & 1u));
            load_tile(f & 3, t0 + f);
        }

        // consumer: wait data
        mbar_wait(mbF + s * 8, (uint32_t)(u >> 2) & 1u);

        const uint32_t sA = sb + s * STAGE;
        #pragma unroll
        for (int ks = 0; ks < 2; ks++) {
            const uint32_t ka = ks * 32;
            uint32_t a[2][4], bh[5][2], bl[5][2];
            LDSM4(a[0][0], a[0][1], a[0][2], a[0][3], sA + aoff + ka);
            LDSM4(a[1][0], a[1][1], a[1][2], a[1][3], sA + aoff + 1280 + ka);
            LDSM4(bh[0][0], bh[0][1], bh[1][0], bh[1][1], sA + boff + ka);
            LDSM4(bh[2][0], bh[2][1], bh[3][0], bh[3][1], sA + boff + 1280 + ka);
            LDSM4(bl[0][0], bl[0][1], bl[1][0], bl[1][1], sA + boff + (OFF_BL - OFF_BH) + ka);
            LDSM4(bl[2][0], bl[2][1], bl[3][0], bl[3][1], sA + boff + (OFF_BL - OFF_BH) + 1280 + ka);
            LDSM4(bh[4][0], bh[4][1], bl[4][0], bl[4][1], sA + boff2m + ka);

            #pragma unroll
            for (int im = 0; im < 2; im++)
                #pragma unroll
                for (int in = 0; in < 5; in++) {
                    mma_f16(acc[im][in], a[im], bh[in]);
                    mma_f16(acc[im][in], a[im], bl[in]);
                }
        }

        // signal stage consumed (one arrive per warp)
        if (lane == 0) MBAR_ARRIVE(mbE + s * 8);
    }

    const size_t outBase = (size_t)z * BATCH * HID;
    #pragma unroll
    for (int im = 0; im < 2; im++) {
        #pragma unroll
        for (int in = 0; in < 5; in++) {
            int row = mbase + wm + im * 16 + grp;
            int col = nbase + wn + in * 8 + qd * 2;
            float b0v = 0.f, b1v = 0.f;
            if (bias) { b0v = bias[col]; b1v = bias[col + 1]; }
            float* d = out + outBase + (size_t)row * HID + col;
            *(float2*)d = make_float2(acc[im][in][0] * invs + b0v,
                                      acc[im][in][1] * invs + b1v);
            *(float2*)(d + 8 * HID) = make_float2(acc[im][in][2] * invs + b0v,
                                                  acc[im][in][3] * invs + b1v);
        }
    }
}

// =====================================================================
// reduce split-K partials + bias -> h0, fused BN partials
// =====================================================================
__global__ __launch_bounds__(256) void reduce_h0_stats(
    const float* __restrict__ part, const float* __restrict__ bias,
    float* __restrict__ h0, float* __restrict__ pstat)
{
    const int blk = blockIdx.x;
    const int t = threadIdx.x;
    const int r0 = blk * (BATCH / NB);
    const int c0 = t, c1 = t + 256;
    const float bi0 = bias[c0];
    float bi1 = 0.f;
    if (c1 < HID) bi1 = bias[c1];

    float s0 = 0.f, q0 = 0.f, s1 = 0.f, q1 = 0.f;
    for (int r = 0; r < BATCH / NB; r++) {
        size_t base = (size_t)(r0 + r) * HID;
        {
            float v = bi0;
            #pragma unroll
            for (int zz = 0; zz < KSPLIT0; zz++)
                v += part[(size_t)zz * BATCH * HID + base + c0];
            h0[base + c0] = v; s0 += v; q0 += v * v;
        }
        if (c1 < HID) {
            float v = bi1;
            #pragma unroll
            for (int zz = 0; zz < KSPLIT0; zz++)
                v += part[(size_t)zz * BATCH * HID + base + c1];
            h0[base + c1] = v; s1 += v; q1 += v * v;
        }
    }
    pstat[c0 * NB + blk] = s0; pstat[SQOFF + c0 * NB + blk] = q0;
    if (c1 < HID) { pstat[c1 * NB + blk] = s1; pstat[SQOFF + c1 * NB + blk] = q1; }
}

// =====================================================================
// BN pass1 / finalize
// =====================================================================
__global__ __launch_bounds__(256) void bn_pass1(
    const float* __restrict__ h, float* __restrict__ pstat)
{
    const int blk = blockIdx.x;
    const int t = threadIdx.x;
    const int r0 = blk * (BATCH / NB);
    const int c0 = t, c1 = t + 256;
    float s0 = 0.f, q0 = 0.f, s1 = 0.f, q1 = 0.f;
    for (int r = 0; r < BATCH / NB; r++) {
        size_t base = (size_t)(r0 + r) * HID;
        float v = h[base + c0]; s0 += v; q0 += v * v;
        if (c1 < HID) { float w = h[base + c1]; s1 += w; q1 += w * w; }
    }
    pstat[c0 * NB + blk] = s0; pstat[SQOFF + c0 * NB + blk] = q0;
    if (c1 < HID) { pstat[c1 * NB + blk] = s1; pstat[SQOFF + c1 * NB + blk] = q1; }
}

__global__ __launch_bounds__(128) void stats_fin(
    const float* __restrict__ pstat, const float* __restrict__ g,
    const float* __restrict__ be, float* __restrict__ sc, float* __restrict__ sh)
{
    __shared__ float ss[128], sq[128];
    const int c = blockIdx.x, t = threadIdx.x;
    float s = 0.f, q = 0.f;
    for (int i = t; i < NB; i += 128) {
        s += pstat[c * NB + i];
        q += pstat[SQOFF + c * NB + i];
    }
    ss[t] = s; sq[t] = q;
    __syncthreads();
    for (int o = 64; o > 0; o >>= 1) {
        if (t < o) { ss[t] += ss[t + o]; sq[t] += sq[t + o]; }
        __syncthreads();
    }
    if (t == 0) {
        double mu = (double)ss[0] / BATCH;
        double var = (double)sq[0] / BATCH - mu * mu;
        if (var < 0.0) var = 0.0;
        float rstd = (float)(1.0 / sqrt(var + (double)EPS));
        float scv = g[c] * rstd;
        sc[c] = scv;
        sh[c] = be[c] - (float)mu * scv;
    }
}

// =====================================================================
// conv_split: relu(bn(h)) -> packed fp16 A tiles for small layers
// =====================================================================
__global__ __launch_bounds__(256) void conv_split(
    const float* __restrict__ h, const float* __restrict__ sc,
    const float* __restrict__ sh, __half* __restrict__ a2)
{
    int idx4 = blockIdx.x * 256 + threadIdx.x;      // < BATCH*K2P/4
    int row = idx4 / (K2P / 4);
    int c4  = (idx4 - row * (K2P / 4)) * 4;
    __half2 o0, o1;
    if (c4 < HID) {
        const float* hp = h + (size_t)row * HID + c4;
        float v0 = fmaxf(hp[0] * sc[c4 + 0] + sh[c4 + 0], 0.0f);
        float v1 = fmaxf(hp[1] * sc[c4 + 1] + sh[c4 + 1], 0.0f);
        float v2 = fmaxf(hp[2] * sc[c4 + 2] + sh[c4 + 2], 0.0f);
        float v3 = fmaxf(hp[3] * sc[c4 + 3] + sh[c4 + 3], 0.0f);
        o0 = __halves2half2(__float2half(v0), __float2half(v1));
        o1 = __halves2half2(__float2half(v2), __float2half(v3));
    } else {
        o0 = __halves2half2(__float2half(0.f), __float2half(0.f));
        o1 = o0;
    }
    size_t o = (((size_t)(row >> 7) * NKT2 + (c4 >> 5)) * 128 + (row & 127)) * 40 + (c4 & 31);
    *(__half2*)(a2 + o)     = o0;
    *(__half2*)(a2 + o + 2) = o1;
}

// =====================================================================
// final dot
// =====================================================================
__global__ __launch_bounds__(256) void final_dot(
    const float* __restrict__ h, const float* __restrict__ scale,
    const float* __restrict__ shift, const float* __restrict__ w3,
    const float* __restrict__ b3, float* __restrict__ out)
{
    const int gtid = blockIdx.x * blockDim.x + threadIdx.x;
    const int warp = gtid >> 5;
    const int lane = gtid & 31;
    if (warp >= BATCH) return;
    float s = 0.0f;
    for (int k = lane; k < HID; k += 32) {
        float v = fmaxf(h[(size_t)warp * HID + k] * scale[k] + shift[k], 0.0f);
        s += v * w3[k];
    }
    #pragma unroll
    for (int off = 16; off > 0; off >>= 1)
        s += __shfl_down_sync(0xFFFFFFFFu, s, off);
    if (lane == 0) out[warp] = s + b3[0];
}

// =====================================================================
// launcher
// =====================================================================
extern "C" void kernel_launch(void* const* d_in, const int* in_sizes, int n_in,
                              void* d_out, int out_size)
{
    const int*   x    = (const int*)  d_in[0];
    const float* emb  = (const float*)d_in[1];
    const float* sw1  = (const float*)d_in[2];
    const float* sb1  = (const float*)d_in[3];
    const float* sw2  = (const float*)d_in[4];
    const float* sb2  = (const float*)d_in[5];
    const float* Wb1  = (const float*)d_in[6];
    const float* Wb2  = (const float*)d_in[7];
    const float* mw0  = (const float*)d_in[8];
    const float* mb0  = (const float*)d_in[9];
    const float* g0   = (const float*)d_in[10];
    const float* be0  = (const float*)d_in[11];
    const float* mw1  = (const float*)d_in[12];
    const float* mb1  = (const float*)d_in[13];
    const float* g1   = (const float*)d_in[14];
    const float* be1  = (const float*)d_in[15];
    const float* mw2  = (const float*)d_in[16];
    const float* mb2  = (const float*)d_in[17];
    const float* g2   = (const float*)d_in[18];
    const float* be2  = (const float*)d_in[19];
    const float* mw3  = (const float*)d_in[20];
    const float* mb3  = (const float*)d_in[21];
    float* out = (float*)d_out;

    __half *a, *bh, *bl, *a2, *w1h, *w1l, *w2h, *w2l;
    float *part, *h0, *h1, *h2, *pstat, *sc, *sh;
    cudaGetSymbolAddress((void**)&a,  d_a);
    cudaGetSymbolAddress((void**)&bh, d_bh);
    cudaGetSymbolAddress((void**)&bl, d_bl);
    cudaGetSymbolAddress((void**)&a2, d_a2);
    cudaGetSymbolAddress((void**)&w1h, d_w2h);   // [0] = layer1
    cudaGetSymbolAddress((void**)&w1l, d_w2l);
    w2h = w1h + (size_t)5 * NKT2 * B_TILE_H;     // [1] = layer2
    w2l = w1l + (size_t)5 * NKT2 * B_TILE_H;
    cudaGetSymbolAddress((void**)&part, d_part);
    cudaGetSymbolAddress((void**)&h0, d_h0);
    cudaGetSymbolAddress((void**)&h1, d_h1);
    cudaGetSymbolAddress((void**)&h2, d_h2);
    cudaGetSymbolAddress((void**)&pstat, d_pstat);
    cudaGetSymbolAddress((void**)&sc, d_scale);
    cudaGetSymbolAddress((void**)&sh, d_shift);

    static int smem_set = 0;
    if (!smem_set) {
        cudaFuncSetAttribute(gemm_f16, cudaFuncAttributeMaxDynamicSharedMemorySize, SMEM_G);
        smem_set = 1;
    }

    // 1) front end -> packed A; mw0 split; small-layer weight splits
    fuse_front<<<BATCH, 256>>>(x, emb, sw1, sb1, sw2, sb2, Wb1, Wb2, a);
    {
        size_t n = (size_t)HID * K1;
        split_b<<<(unsigned)((n + 255) / 256), 256>>>(mw0, bh, bl);
    }
    wsplit2<<<HID * K2P / 256, 256>>>(mw1, mw2, w1h, w1l, w2h, w2l);

    // 2) GEMM0 (split-K=9, 2 CTAs/SM, bulk pipeline) + fused reduce/BN
    {
        dim3 grid(HID / BN, BATCH / BM, KSPLIT0);   // (5, 32, 9) = 1440 CTAs
        gemm_f16<<<grid, 256, SMEM_G>>>(a, bh, bl, part, nullptr, INVS0, NKT0, KSPLIT0);
        reduce_h0_stats<<<NB, 256>>>(part, mb0, h0, pstat);
        stats_fin<<<HID, 128>>>(pstat, g0, be0, sc + 0 * HID, sh + 0 * HID);
    }

    // 3) layer 1
    conv_split<<<BATCH * K2P / 4 / 256, 256>>>(h0, sc + 0 * HID, sh + 0 * HID, a2);
    {
        dim3 grid(HID / BN, BATCH / BM, 1);
        gemm_f16<<<grid, 256, SMEM_G>>>(a2, w1h, w1l, h1, mb1, INVS2, NKT2, 1);
    }
    bn_pass1<<<NB, 256>>>(h1, pstat);
    stats_fin<<<HID, 128>>>(pstat, g1, be1, sc + 1 * HID, sh + 1 * HID);

    // 4) layer 2
    conv_split<<<BATCH * K2P / 4 / 256, 256>>>(h1, sc + 1 * HID, sh + 1 * HID, a2);
    {
        dim3 grid(HID / BN, BATCH / BM, 1);
        gemm_f16<<<grid, 256, SMEM_G>>>(a2, w2h, w2l, h2, mb2, INVS2, NKT2, 1);
    }
    bn_pass1<<<NB, 256>>>(h2, pstat);
    stats_fin<<<HID, 128>>>(pstat, g2, be2, sc + 2 * HID, sh + 2 * HID);

    // 5) final dot
    final_dot<<<(BATCH * 32 + 255) / 256, 256>>>(h2, sc + 2 * HID, sh + 2 * HID,
                                                 mw3, mb3, out);
}

// round 17
// speedup vs baseline: 1.3369x; 1.3369x over previous
#include <cuda_runtime.h>
#include <cuda_fp16.h>
#include <math.h>
#include <stdint.h>

// ---------------- problem constants ----------------
#define BATCH 4096
#define NF    39
#define NE    16
#define NPAIR 741
#define K1    (2 * NPAIR * NE)    // 23712
#define NKT0  741                 // K1/32 k-tiles
#define HID   400
#define K2P   416                 // HID padded for small layers
#define NKT2  13                  // K2P/32
#define EPS   1e-5f

// quantization scales
#define SA0   8192.0f
#define SB0   4096.0f
#define INVS0 (1.0f / (SA0 * SB0))
#define SB2   4096.0f
#define INVS2 (1.0f / SB2)

// ---------------- fp16 2-product GEMM tiling (4-stage, 2 CTAs/SM) ----------------
#define BM 128
#define BN 80
#define A_ROWB 80                 // smem row stride bytes (32 halves + 8 pad halves)
#define OFF_BH  10240             // A: 128*80
#define OFF_BL  16640             // +80*80
#define STAGE   23040
#define NSTAGE  4
#define SMEM_G  (STAGE * NSTAGE + 64)  // + mbarriers
#define KSPLIT0 9
#define NB      512
#define SQOFF   (HID * NB)

// packed tile sizes (halves)
#define A_TILE_H 5120             // 128 rows * 40 halves
#define B_TILE_H 3200             // 80 rows * 40 halves

// ---------------- scratch (packed tile-major layouts) ----------------
__device__ __half d_a[(size_t)32 * NKT0 * A_TILE_H];      // [mtile][kt][128][40]
__device__ __half d_bh[(size_t)5 * NKT0 * B_TILE_H];      // [ntile][kt][80][40]
__device__ __half d_bl[(size_t)5 * NKT0 * B_TILE_H];
__device__ float d_part[(size_t)KSPLIT0 * BATCH * HID];
__device__ __half d_a2[(size_t)32 * NKT2 * A_TILE_H];
__device__ __half d_w2h[2][(size_t)5 * NKT2 * B_TILE_H];
__device__ __half d_w2l[2][(size_t)5 * NKT2 * B_TILE_H];
__device__ float d_h0[BATCH * HID];
__device__ float d_h1[BATCH * HID];
__device__ float d_h2[BATCH * HID];
__device__ float d_pstat[2 * NB * HID];
__device__ float d_scale[3][HID];
__device__ float d_shift[3][HID];

// ---------------- helpers ----------------
__device__ __forceinline__ uint32_t smem_u32(const void* p) {
    uint32_t a;
    asm("{ .reg .u64 t; cvta.to.shared.u64 t, %1; cvt.u32.u64 %0, t; }" : "=r"(a) : "l"(p));
    return a;
}

#define CP_BULK(dst, src, bytes, mbar) \
    asm volatile("cp.async.bulk.shared::cta.global.mbarrier::complete_tx::bytes [%0], [%1], %2, [%3];" \
        :: "r"(dst), "l"(src), "r"(bytes), "r"(mbar) : "memory")
#define MBAR_INIT(a, c)   asm volatile("mbarrier.init.shared.b64 [%0], %1;" :: "r"(a), "r"(c) : "memory")
#define MBAR_EXPECT(a, b) asm volatile("mbarrier.arrive.expect_tx.shared.b64 _, [%0], %1;" :: "r"(a), "r"(b) : "memory")
#define FENCE_ASYNC()     asm volatile("fence.proxy.async.shared::cta;" ::: "memory")

__device__ __forceinline__ void mbar_wait(uint32_t mbar, uint32_t parity) {
    asm volatile(
        "{\n\t.reg .pred P1;\n\t"
        "WAIT_LOOP_%=:\n\t"
        "mbarrier.try_wait.parity.acquire.cta.shared::cta.b64 P1, [%0], %1, 0x989680;\n\t"
        "@P1 bra.uni WAIT_DONE_%=;\n\t"
        "bra.uni WAIT_LOOP_%=;\n\t"
        "WAIT_DONE_%=:\n\t}"
        :: "r"(mbar), "r"(parity) : "memory");
}

#define LDSM4(r0, r1, r2, r3, a) \
    asm volatile("ldmatrix.sync.aligned.m8n8.x4.shared.b16 {%0,%1,%2,%3}, [%4];" \
        : "=r"(r0), "=r"(r1), "=r"(r2), "=r"(r3) : "r"(a))
#define LDSM2(r0, r1, a) \
    asm volatile("ldmatrix.sync.aligned.m8n8.x2.shared.b16 {%0,%1}, [%2];" \
        : "=r"(r0), "=r"(r1) : "r"(a))

__device__ __forceinline__ void mma_f16(float* c, const uint32_t* a, const uint32_t* b) {
    asm volatile(
        "mma.sync.aligned.m16n8k16.row.col.f32.f16.f16.f32 "
        "{%0,%1,%2,%3}, {%4,%5,%6,%7}, {%8,%9}, {%0,%1,%2,%3};"
        : "+f"(c[0]), "+f"(c[1]), "+f"(c[2]), "+f"(c[3])
        : "r"(a[0]), "r"(a[1]), "r"(a[2]), "r"(a[3]), "r"(b[0]), "r"(b[1]));
}

// =====================================================================
// Kernel 1: gather + SENET + bilinear -> packed A tiles (scaled fp16)
// =====================================================================
__global__ __launch_bounds__(256) void fuse_front(
    const int* __restrict__ x,
    const float* __restrict__ emb,
    const float* __restrict__ w1, const float* __restrict__ b1,
    const float* __restrict__ w2, const float* __restrict__ b2,
    const float* __restrict__ Wb1, const float* __restrict__ Wb2,
    __half* __restrict__ a_out)
{
    __shared__ float xe[NF][NE];
    __shared__ float xs[NF][NE];
    __shared__ float p1[NF][NE];
    __shared__ float p2[NF][NE];
    __shared__ float zf[NF], av[NF], af[NF];
    __shared__ unsigned char ii[NPAIR], jj[NPAIR];
    __shared__ int is64;

    const int b = blockIdx.x;
    const int tid = threadIdx.x;

    if (tid == 0) {
        int f64 = 1;
        for (int w = 1; w < 2 * NF; w += 2)
            if (x[w] != 0) { f64 = 0; break; }
        is64 = f64;
    }
    for (int k = tid; k < NPAIR; k += 256) {
        int i = 0, rem = k;
        while (rem >= NF - 1 - i) { rem -= NF - 1 - i; i++; }
        ii[k] = (unsigned char)i;
        jj[k] = (unsigned char)(i + 1 + rem);
    }
    __syncthreads();

    for (int idx = tid; idx < NF * NE; idx += 256) {
        int f = idx >> 4, e = idx & 15;
        int xv = is64 ? x[2 * (b * NF + f)] : x[b * NF + f];
        xe[f][e] = emb[(xv + 1000 * f) * NE + e];
    }
    __syncthreads();

    if (tid < NF) {
        float m = xe[tid][0];
        #pragma unroll
        for (int e = 1; e < NE; e++) m = fmaxf(m, xe[tid][e]);
        zf[tid] = m;
    }
    __syncthreads();
    if (tid < NF) {
        float s = b1[tid];
        for (int j = 0; j < NF; j++) s += zf[j] * w1[tid * NF + j];
        av[tid] = fmaxf(s, 0.0f);
    }
    __syncthreads();
    if (tid < NF) {
        float s = b2[tid];
        for (int j = 0; j < NF; j++) s += av[j] * w2[tid * NF + j];
        af[tid] = fmaxf(s, 0.0f);
    }
    __syncthreads();

    for (int idx = tid; idx < NF * NE; idx += 256) {
        int f = idx >> 4, d = idx & 15;
        float s1 = 0.0f, s2 = 0.0f;
        #pragma unroll
        for (int e = 0; e < NE; e++) {
            float v = xe[f][e];
            s1 += v * Wb1[d * NE + e];
            s2 += v * Wb2[d * NE + e];
        }
        p1[f][d] = s1;
        p2[f][d] = af[f] * s2;
        xs[f][d] = af[f] * xe[f][d];
    }
    __syncthreads();

    // packed half2 stores: dest = [b>>7][kt][b&127][pos]
    const size_t mtb = (size_t)(b >> 7) * NKT0;
    const int mrow = b & 127;
    const int HALF_N = NPAIR * NE / 2;   // 5928
    for (int idx2 = tid; idx2 < HALF_N; idx2 += 256) {
        int k = idx2 >> 3;
        int e = (idx2 & 7) * 2;
        int i = ii[k], j = jj[k];
        float v1a = p1[i][e]     * xe[j][e];
        float v1b = p1[i][e + 1] * xe[j][e + 1];
        float v2a = p2[i][e]     * xs[j][e];
        float v2b = p2[i][e + 1] * xs[j][e + 1];
        int gk0 = idx2 * 2;
        int gk1 = gk0 + NPAIR * NE;
        size_t o0 = (mtb + (gk0 >> 5)) * A_TILE_H + mrow * 40 + (gk0 & 31);
        size_t o1 = (mtb + (gk1 >> 5)) * A_TILE_H + mrow * 40 + (gk1 & 31);
        *(__half2*)(a_out + o0) = __halves2half2(__float2half(v1a * SA0), __float2half(v1b * SA0));
        *(__half2*)(a_out + o1) = __halves2half2(__float2half(v2a * SA0), __float2half(v2b * SA0));
    }
}

// =====================================================================
// Kernel 1b: split mw0 rows into scaled fp16 hi/lo (packed B tiles)
// =====================================================================
__global__ __launch_bounds__(256) void split_b(
    const float* __restrict__ w, __half* __restrict__ bh,
    __half* __restrict__ bl)
{
    size_t i = (size_t)blockIdx.x * 256 + threadIdx.x;
    size_t n = (size_t)HID * K1;
    if (i < n) {
        int row = (int)(i / K1);
        int k   = (int)(i - (size_t)row * K1);
        float t = w[i] * SB0;
        __half h = __float2half(t);
        size_t o = (((size_t)(row / 80) * NKT0 + (k >> 5)) * 80 + (row % 80)) * 40 + (k & 31);
        bh[o] = h;
        bl[o] = __float2half(t - __half2float(h));
    }
}

// =====================================================================
// Kernel 1c: split BOTH small-layer weights -> packed fp16 hi/lo tiles
// =====================================================================
__global__ __launch_bounds__(256) void wsplit2(
    const float* __restrict__ wA, const float* __restrict__ wB,
    __half* __restrict__ hA, __half* __restrict__ lA,
    __half* __restrict__ hB, __half* __restrict__ lB)
{
    int idx = blockIdx.x * 256 + threadIdx.x;    // < HID*K2P
    int row = idx / K2P, col = idx - row * K2P;
    float vA = (col < HID) ? wA[row * HID + col] * SB2 : 0.0f;
    float vB = (col < HID) ? wB[row * HID + col] * SB2 : 0.0f;
    __half a = __float2half(vA);
    __half b = __float2half(vB);
    size_t o = (((size_t)(row / 80) * NKT2 + (col >> 5)) * 80 + (row % 80)) * 40 + (col & 31);
    hA[o] = a; lA[o] = __float2half(vA - __half2float(a));
    hB[o] = b; lB[o] = __float2half(vB - __half2float(b));
}

// =====================================================================
// gemm_f16: 2-product fp16 GEMM with cp.async.bulk tile loads
//   CTA 128x80, BK=32, 4-stage, 2 CTAs/SM; warp-0-only full wait
// =====================================================================
__global__ __launch_bounds__(256, 2) void gemm_f16(
    const __half* __restrict__ A,
    const __half* __restrict__ Bh, const __half* __restrict__ Bl,
    float* __restrict__ out, const float* __restrict__ bias,
    float invs, int nkt, int ksplit)
{
    extern __shared__ char smem[];
    const uint32_t sb = smem_u32(smem);
    const uint32_t mbb = sb + STAGE * NSTAGE;    // 4 mbarriers
    const int tid  = threadIdx.x;
    const int wid  = tid >> 5;
    const int lane = tid & 31;

    const int nbase = blockIdx.x * BN;
    const int mbase = blockIdx.y * BM;
    const int z     = blockIdx.z;

    const int qt = nkt / ksplit, rt = nkt % ksplit;
    const int t0 = z * qt + (z < rt ? z : rt);
    const int T  = qt + (z < rt ? 1 : 0);

    const size_t aTB = (size_t)blockIdx.y * nkt;
    const size_t bTB = (size_t)blockIdx.x * nkt;

    const int wm = (wid & 3) * 32;
    const int wn = (wid >> 2) * 40;
    const int grp = lane >> 2;
    const int qd  = lane & 3;

    const uint32_t aoff = (uint32_t)((wm + (lane & 15)) * A_ROWB + ((lane >> 4) * 16));
    const int rowB = (lane & 7) + ((lane >> 4) << 3);
    const int kB   = ((lane >> 3) & 1) * 16;
    const uint32_t boff  = (uint32_t)(OFF_BH + (wn + rowB) * A_ROWB + kB);
    const uint32_t boff2 = (uint32_t)(OFF_BH + (wn + 32 + (lane & 7)) * A_ROWB + kB);

    float acc[2][5][4];
    #pragma unroll
    for (int im = 0; im < 2; im++)
        #pragma unroll
        for (int in = 0; in < 5; in++)
            #pragma unroll
            for (int r = 0; r < 4; r++) acc[im][in][r] = 0.0f;

    auto load_tile = [&](int s, int t) {
        const uint32_t st = sb + s * STAGE;
        const uint32_t mbar = mbb + s * 8;
        MBAR_EXPECT(mbar, (uint32_t)STAGE);
        CP_BULK(st,          A  + (aTB + t) * A_TILE_H, (uint32_t)(A_TILE_H * 2), mbar);
        CP_BULK(st + OFF_BH, Bh + (bTB + t) * B_TILE_H, (uint32_t)(B_TILE_H * 2), mbar);
        CP_BULK(st + OFF_BL, Bl + (bTB + t) * B_TILE_H, (uint32_t)(B_TILE_H * 2), mbar);
    };

    if (tid == 0) {
        #pragma unroll
        for (int s = 0; s < NSTAGE; s++) MBAR_INIT(mbb + s * 8, 1);
        FENCE_ASYNC();
        load_tile(0, t0);
        load_tile(1, t0 + 1);
        load_tile(2, t0 + 2);
    }
    __syncthreads();

    for (int u = 0; u < T; ++u) {
        const int s = u & 3;
        // warp 0 waits for the stage's bulk copies; barrier releases the rest
        if (wid == 0) mbar_wait(mbb + s * 8, (u >> 2) & 1);
        __syncthreads();

        if (u + 3 < T && tid == 0) load_tile((u + 3) & 3, t0 + u + 3);

        const uint32_t sA = sb + s * STAGE;
        #pragma unroll
        for (int ks = 0; ks < 2; ks++) {
            const uint32_t ka = ks * 32;
            uint32_t a[2][4], bh[5][2], bl[5][2];
            LDSM4(a[0][0], a[0][1], a[0][2], a[0][3], sA + aoff + ka);
            LDSM4(a[1][0], a[1][1], a[1][2], a[1][3], sA + aoff + 1280 + ka);
            LDSM4(bh[0][0], bh[0][1], bh[1][0], bh[1][1], sA + boff + ka);
            LDSM4(bh[2][0], bh[2][1], bh[3][0], bh[3][1], sA + boff + 1280 + ka);
            LDSM2(bh[4][0], bh[4][1], sA + boff2 + ka);
            LDSM4(bl[0][0], bl[0][1], bl[1][0], bl[1][1], sA + boff + (OFF_BL - OFF_BH) + ka);
            LDSM4(bl[2][0], bl[2][1], bl[3][0], bl[3][1], sA + boff + (OFF_BL - OFF_BH) + 1280 + ka);
            LDSM2(bl[4][0], bl[4][1], sA + boff2 + (OFF_BL - OFF_BH) + ka);

            #pragma unroll
            for (int im = 0; im < 2; im++)
                #pragma unroll
                for (int in = 0; in < 5; in++) {
                    mma_f16(acc[im][in], a[im], bh[in]);
                    mma_f16(acc[im][in], a[im], bl[in]);
                }
        }
    }

    const size_t outBase = (size_t)z * BATCH * HID;
    #pragma unroll
    for (int im = 0; im < 2; im++) {
        #pragma unroll
        for (int in = 0; in < 5; in++) {
            int row = mbase + wm + im * 16 + grp;
            int col = nbase + wn + in * 8 + qd * 2;
            float b0v = 0.f, b1v = 0.f;
            if (bias) { b0v = bias[col]; b1v = bias[col + 1]; }
            float* d = out + outBase + (size_t)row * HID + col;
            *(float2*)d = make_float2(acc[im][in][0] * invs + b0v,
                                      acc[im][in][1] * invs + b1v);
            *(float2*)(d + 8 * HID) = make_float2(acc[im][in][2] * invs + b0v,
                                                  acc[im][in][3] * invs + b1v);
        }
    }
}

// =====================================================================
// reduce split-K partials + bias -> h0, fused BN partials
// =====================================================================
__global__ __launch_bounds__(256) void reduce_h0_stats(
    const float* __restrict__ part, const float* __restrict__ bias,
    float* __restrict__ h0, float* __restrict__ pstat)
{
    const int blk = blockIdx.x;
    const int t = threadIdx.x;
    const int r0 = blk * (BATCH / NB);
    const int c0 = t, c1 = t + 256;
    const float bi0 = bias[c0];
    float bi1 = 0.f;
    if (c1 < HID) bi1 = bias[c1];

    float s0 = 0.f, q0 = 0.f, s1 = 0.f, q1 = 0.f;
    for (int r = 0; r < BATCH / NB; r++) {
        size_t base = (size_t)(r0 + r) * HID;
        {
            float v = bi0;
            #pragma unroll
            for (int zz = 0; zz < KSPLIT0; zz++)
                v += part[(size_t)zz * BATCH * HID + base + c0];
            h0[base + c0] = v; s0 += v; q0 += v * v;
        }
        if (c1 < HID) {
            float v = bi1;
            #pragma unroll
            for (int zz = 0; zz < KSPLIT0; zz++)
                v += part[(size_t)zz * BATCH * HID + base + c1];
            h0[base + c1] = v; s1 += v; q1 += v * v;
        }
    }
    pstat[c0 * NB + blk] = s0; pstat[SQOFF + c0 * NB + blk] = q0;
    if (c1 < HID) { pstat[c1 * NB + blk] = s1; pstat[SQOFF + c1 * NB + blk] = q1; }
}

// =====================================================================
// BN pass1 / finalize
// =====================================================================
__global__ __launch_bounds__(256) void bn_pass1(
    const float* __restrict__ h, float* __restrict__ pstat)
{
    const int blk = blockIdx.x;
    const int t = threadIdx.x;
    const int r0 = blk * (BATCH / NB);
    const int c0 = t, c1 = t + 256;
    float s0 = 0.f, q0 = 0.f, s1 = 0.f, q1 = 0.f;
    for (int r = 0; r < BATCH / NB; r++) {
        size_t base = (size_t)(r0 + r) * HID;
        float v = h[base + c0]; s0 += v; q0 += v * v;
        if (c1 < HID) { float w = h[base + c1]; s1 += w; q1 += w * w; }
    }
    pstat[c0 * NB + blk] = s0; pstat[SQOFF + c0 * NB + blk] = q0;
    if (c1 < HID) { pstat[c1 * NB + blk] = s1; pstat[SQOFF + c1 * NB + blk] = q1; }
}

__global__ __launch_bounds__(128) void stats_fin(
    const float* __restrict__ pstat, const float* __restrict__ g,
    const float* __restrict__ be, float* __restrict__ sc, float* __restrict__ sh)
{
    __shared__ float ss[128], sq[128];
    const int c = blockIdx.x, t = threadIdx.x;
    float s = 0.f, q = 0.f;
    for (int i = t; i < NB; i += 128) {
        s += pstat[c * NB + i];
        q += pstat[SQOFF + c * NB + i];
    }
    ss[t] = s; sq[t] = q;
    __syncthreads();
    for (int o = 64; o > 0; o >>= 1) {
        if (t < o) { ss[t] += ss[t + o]; sq[t] += sq[t + o]; }
        __syncthreads();
    }
    if (t == 0) {
        double mu = (double)ss[0] / BATCH;
        double var = (double)sq[0] / BATCH - mu * mu;
        if (var < 0.0) var = 0.0;
        float rstd = (float)(1.0 / sqrt(var + (double)EPS));
        float scv = g[c] * rstd;
        sc[c] = scv;
        sh[c] = be[c] - (float)mu * scv;
    }
}

// =====================================================================
// conv_split: relu(bn(h)) -> packed fp16 A tiles for small layers
// =====================================================================
__global__ __launch_bounds__(256) void conv_split(
    const float* __restrict__ h, const float* __restrict__ sc,
    const float* __restrict__ sh, __half* __restrict__ a2)
{
    int idx4 = blockIdx.x * 256 + threadIdx.x;      // < BATCH*K2P/4
    int row = idx4 / (K2P / 4);
    int c4  = (idx4 - row * (K2P / 4)) * 4;
    __half2 o0, o1;
    if (c4 < HID) {
        const float* hp = h + (size_t)row * HID + c4;
        float v0 = fmaxf(hp[0] * sc[c4 + 0] + sh[c4 + 0], 0.0f);
        float v1 = fmaxf(hp[1] * sc[c4 + 1] + sh[c4 + 1], 0.0f);
        float v2 = fmaxf(hp[2] * sc[c4 + 2] + sh[c4 + 2], 0.0f);
        float v3 = fmaxf(hp[3] * sc[c4 + 3] + sh[c4 + 3], 0.0f);
        o0 = __halves2half2(__float2half(v0), __float2half(v1));
        o1 = __halves2half2(__float2half(v2), __float2half(v3));
    } else {
        o0 = __halves2half2(__float2half(0.f), __float2half(0.f));
        o1 = o0;
    }
    size_t o = (((size_t)(row >> 7) * NKT2 + (c4 >> 5)) * 128 + (row & 127)) * 40 + (c4 & 31);
    *(__half2*)(a2 + o)     = o0;
    *(__half2*)(a2 + o + 2) = o1;
}

// =====================================================================
// final dot
// =====================================================================
__global__ __launch_bounds__(256) void final_dot(
    const float* __restrict__ h, const float* __restrict__ scale,
    const float* __restrict__ shift, const float* __restrict__ w3,
    const float* __restrict__ b3, float* __restrict__ out)
{
    const int gtid = blockIdx.x * blockDim.x + threadIdx.x;
    const int warp = gtid >> 5;
    const int lane = gtid & 31;
    if (warp >= BATCH) return;
    float s = 0.0f;
    for (int k = lane; k < HID; k += 32) {
        float v = fmaxf(h[(size_t)warp * HID + k] * scale[k] + shift[k], 0.0f);
        s += v * w3[k];
    }
    #pragma unroll
    for (int off = 16; off > 0; off >>= 1)
        s += __shfl_down_sync(0xFFFFFFFFu, s, off);
    if (lane == 0) out[warp] = s + b3[0];
}

// =====================================================================
// launcher
// =====================================================================
extern "C" void kernel_launch(void* const* d_in, const int* in_sizes, int n_in,
                              void* d_out, int out_size)
{
    const int*   x    = (const int*)  d_in[0];
    const float* emb  = (const float*)d_in[1];
    const float* sw1  = (const float*)d_in[2];
    const float* sb1  = (const float*)d_in[3];
    const float* sw2  = (const float*)d_in[4];
    const float* sb2  = (const float*)d_in[5];
    const float* Wb1  = (const float*)d_in[6];
    const float* Wb2  = (const float*)d_in[7];
    const float* mw0  = (const float*)d_in[8];
    const float* mb0  = (const float*)d_in[9];
    const float* g0   = (const float*)d_in[10];
    const float* be0  = (const float*)d_in[11];
    const float* mw1  = (const float*)d_in[12];
    const float* mb1  = (const float*)d_in[13];
    const float* g1   = (const float*)d_in[14];
    const float* be1  = (const float*)d_in[15];
    const float* mw2  = (const float*)d_in[16];
    const float* mb2  = (const float*)d_in[17];
    const float* g2   = (const float*)d_in[18];
    const float* be2  = (const float*)d_in[19];
    const float* mw3  = (const float*)d_in[20];
    const float* mb3  = (const float*)d_in[21];
    float* out = (float*)d_out;

    __half *a, *bh, *bl, *a2, *w1h, *w1l, *w2h, *w2l;
    float *part, *h0, *h1, *h2, *pstat, *sc, *sh;
    cudaGetSymbolAddress((void**)&a,  d_a);
    cudaGetSymbolAddress((void**)&bh, d_bh);
    cudaGetSymbolAddress((void**)&bl, d_bl);
    cudaGetSymbolAddress((void**)&a2, d_a2);
    cudaGetSymbolAddress((void**)&w1h, d_w2h);   // [0] = layer1
    cudaGetSymbolAddress((void**)&w1l, d_w2l);
    w2h = w1h + (size_t)5 * NKT2 * B_TILE_H;     // [1] = layer2
    w2l = w1l + (size_t)5 * NKT2 * B_TILE_H;
    cudaGetSymbolAddress((void**)&part, d_part);
    cudaGetSymbolAddress((void**)&h0, d_h0);
    cudaGetSymbolAddress((void**)&h1, d_h1);
    cudaGetSymbolAddress((void**)&h2, d_h2);
    cudaGetSymbolAddress((void**)&pstat, d_pstat);
    cudaGetSymbolAddress((void**)&sc, d_scale);
    cudaGetSymbolAddress((void**)&sh, d_shift);

    static int smem_set = 0;
    if (!smem_set) {
        cudaFuncSetAttribute(gemm_f16, cudaFuncAttributeMaxDynamicSharedMemorySize, SMEM_G);
        smem_set = 1;
    }

    // 1) front end -> packed A; mw0 split; small-layer weight splits
    fuse_front<<<BATCH, 256>>>(x, emb, sw1, sb1, sw2, sb2, Wb1, Wb2, a);
    {
        size_t n = (size_t)HID * K1;
        split_b<<<(unsigned)((n + 255) / 256), 256>>>(mw0, bh, bl);
    }
    wsplit2<<<HID * K2P / 256, 256>>>(mw1, mw2, w1h, w1l, w2h, w2l);

    // 2) GEMM0 (split-K=9, 2 CTAs/SM, bulk-copy pipeline) + fused reduce/BN
    {
        dim3 grid(HID / BN, BATCH / BM, KSPLIT0);   // (5, 32, 9) = 1440 CTAs
        gemm_f16<<<grid, 256, SMEM_G>>>(a, bh, bl, part, nullptr, INVS0, NKT0, KSPLIT0);
        reduce_h0_stats<<<NB, 256>>>(part, mb0, h0, pstat);
        stats_fin<<<HID, 128>>>(pstat, g0, be0, sc + 0 * HID, sh + 0 * HID);
    }

    // 3) layer 1
    conv_split<<<BATCH * K2P / 4 / 256, 256>>>(h0, sc + 0 * HID, sh + 0 * HID, a2);
    {
        dim3 grid(HID / BN, BATCH / BM, 1);
        gemm_f16<<<grid, 256, SMEM_G>>>(a2, w1h, w1l, h1, mb1, INVS2, NKT2, 1);
    }
    bn_pass1<<<NB, 256>>>(h1, pstat);
    stats_fin<<<HID, 128>>>(pstat, g1, be1, sc + 1 * HID, sh + 1 * HID);

    // 4) layer 2
    conv_split<<<BATCH * K2P / 4 / 256, 256>>>(h1, sc + 1 * HID, sh + 1 * HID, a2);
    {
        dim3 grid(HID / BN, BATCH / BM, 1);
        gemm_f16<<<grid, 256, SMEM_G>>>(a2, w2h, w2l, h2, mb2, INVS2, NKT2, 1);
    }
    bn_pass1<<<NB, 256>>>(h2, pstat);
    stats_fin<<<HID, 128>>>(pstat, g2, be2, sc + 2 * HID, sh + 2 * HID);

    // 5) final dot
    final_dot<<<(BATCH * 32 + 255) / 256, 256>>>(h2, sc + 2 * HID, sh + 2 * HID,
                                                 mw3, mb3, out);
}